// round 3
// baseline (speedup 1.0000x reference)
#include <cuda_runtime.h>
#include <cstdint>

// ---------------------------------------------------------------------------
// FeatureProjection: 4-level bilinear gather + concat
//   feat0 [16, 64,56,56], feat1 [16,128,28,28], feat2 [16,256,14,14],
//   feat3 [16,512, 7, 7], pc [16,4096,3]  ->  out [16,4096,960] fp32
//
//   1) transpose each level NCHW -> NHWC into __device__ scratch (coalesced
//      both sides via 32x32 shared tile). 24MB total, stays L2-resident.
//   2) flat kernel over B*N*240 float4 outputs: projection math redone per
//      thread, 4 contiguous float4 corner gathers, 1 coalesced float4 store.
//
//   NUMERICS: XLA rewrites w/(223/(W-1)) into w * f32(1/f32(223/(W-1))).
//   ~83% of points saturate the clip and land within half-ULP of an integer
//   coordinate; multiply-by-reciprocal vs true division decides whether the
//   bilinear weights are all-zero there. We replicate the multiply form.
// ---------------------------------------------------------------------------

#define B_    16
#define N_    4096

// NHWC scratch (float4-aligned)
__device__ __align__(16) float g_t0[16 * 56 * 56 * 64];
__device__ __align__(16) float g_t1[16 * 28 * 28 * 128];
__device__ __align__(16) float g_t2[16 * 14 * 14 * 256];
__device__ __align__(16) float g_t3[16 * 7 * 7 * 512];

// f32 constants exactly as XLA folds them: c = f32(223/(W-1)), r = f32(1/c)
__host__ __device__ constexpr float kC0 = (float)(223.0 / 55.0);
__host__ __device__ constexpr float kC1 = (float)(223.0 / 27.0);
__host__ __device__ constexpr float kC2 = (float)(223.0 / 13.0);
__host__ __device__ constexpr float kC3 = (float)(223.0 / 6.0);

// ---------------- transpose: [C, HW] -> [HW, C] per batch -------------------
__global__ void transpose_kernel(const float* __restrict__ in, int level)
{
    float* out;
    int C, HW;
    switch (level) {
        case 0:  out = g_t0; C = 64;  HW = 56 * 56; break;
        case 1:  out = g_t1; C = 128; HW = 28 * 28; break;
        case 2:  out = g_t2; C = 256; HW = 14 * 14; break;
        default: out = g_t3; C = 512; HW = 7 * 7;   break;
    }
    __shared__ float tile[32][33];

    const int b = blockIdx.z;
    const float* bin  = in  + (size_t)b * C * HW;
    float*       bout = out + (size_t)b * C * HW;

    int s0 = blockIdx.x * 32;   // spatial tile origin
    int c0 = blockIdx.y * 32;   // channel tile origin

    int s = s0 + threadIdx.x;
    #pragma unroll
    for (int j = 0; j < 32; j += 8) {
        int c = c0 + threadIdx.y + j;
        if (s < HW && c < C)
            tile[threadIdx.y + j][threadIdx.x] = bin[(size_t)c * HW + s];
    }
    __syncthreads();

    int c = c0 + threadIdx.x;
    #pragma unroll
    for (int j = 0; j < 32; j += 8) {
        int ss = s0 + threadIdx.y + j;
        if (c < C && ss < HW)
            bout[(size_t)ss * C + c] = tile[threadIdx.x][threadIdx.y + j];
    }
}

// ---------------- main projection kernel -----------------------------------
// float4 outputs per point: 64/4 + 128/4 + 256/4 + 512/4 = 240
// level boundaries (float4 units): [0,16) [16,48) [48,112) [112,240)
__global__ void __launch_bounds__(256) proj_kernel(const float* __restrict__ pc,
                                                   float4* __restrict__ out,
                                                   int total)
{
    int idx = blockIdx.x * blockDim.x + threadIdx.x;
    if (idx >= total) return;

    int point = idx / 240;
    int i     = idx - point * 240;
    int b     = point >> 12;          // N = 4096

    const float* pp = pc + (size_t)point * 3;
    float X = __ldg(pp + 0);
    float Y = __ldg(pp + 1);
    float Z = __ldg(pp + 2);

    const float4* base;
    int c4, H, C4;
    float rscale;   // f32 reciprocal of the f32 constant, XLA's folded form
    if (i < 16)       { base = (const float4*)g_t0; c4 = i;       H = 56; C4 = 16;  rscale = 1.0f / kC0; }
    else if (i < 48)  { base = (const float4*)g_t1; c4 = i - 16;  H = 28; C4 = 32;  rscale = 1.0f / kC1; }
    else if (i < 112) { base = (const float4*)g_t2; c4 = i - 48;  H = 14; C4 = 64;  rscale = 1.0f / kC2; }
    else              { base = (const float4*)g_t3; c4 = i - 112; H = 7;  C4 = 128; rscale = 1.0f / kC3; }
    const int W = H;

    float az = fabsf(Z);
    // projection: true IEEE division (non-constant divisor stays fdiv in XLA)
    float w = fminf(fmaxf(__fdiv_rn(420.0f * X, az) + 111.5f, 0.0f), 223.0f);
    float h = fminf(fmaxf(__fdiv_rn(420.0f * Y, az) + 111.5f, 0.0f), 223.0f);
    // XLA: divide-by-constant -> multiply-by-reciprocal (exact replication)
    float x = __fmul_rn(w, rscale);
    float y = __fmul_rn(h, rscale);

    float x1f = floorf(x), x2f = ceilf(x);
    float y1f = floorf(y), y2f = ceilf(y);

    // weights from UNclamped floats (faithful to reference)
    float w11 = (x2f - x) * (y2f - y);
    float w21 = (x - x1f) * (y2f - y);
    float w12 = (x2f - x) * (y - y1f);
    float w22 = (x - x1f) * (y - y1f);

    // gather indices clamped (XLA gather clamps OOB; ceil can hit W here)
    int x1 = min(max((int)x1f, 0), W - 1);
    int x2 = min(max((int)x2f, 0), W - 1);
    int y1 = min(max((int)y1f, 0), W - 1);
    int y2 = min(max((int)y2f, 0), W - 1);

    const float4* pb = base + (size_t)b * H * W * C4;
    int r1 = x1 * W * C4;
    int r2 = x2 * W * C4;
    float4 v11 = __ldg(pb + r1 + y1 * C4 + c4);
    float4 v21 = __ldg(pb + r2 + y1 * C4 + c4);
    float4 v12 = __ldg(pb + r1 + y2 * C4 + c4);
    float4 v22 = __ldg(pb + r2 + y2 * C4 + c4);

    float4 r;
    r.x = v11.x * w11 + v21.x * w21 + v12.x * w12 + v22.x * w22;
    r.y = v11.y * w11 + v21.y * w21 + v12.y * w12 + v22.y * w22;
    r.z = v11.z * w11 + v21.z * w21 + v12.z * w12 + v22.z * w22;
    r.w = v11.w * w11 + v21.w * w21 + v12.w * w12 + v22.w * w22;

    out[idx] = r;
}

// ---------------------------------------------------------------------------
extern "C" void kernel_launch(void* const* d_in, const int* in_sizes, int n_in,
                              void* d_out, int out_size)
{
    const float* f0 = (const float*)d_in[0];
    const float* f1 = (const float*)d_in[1];
    const float* f2 = (const float*)d_in[2];
    const float* f3 = (const float*)d_in[3];
    const float* pc = (const float*)d_in[4];

    dim3 tb(32, 8, 1);
    transpose_kernel<<<dim3((3136 + 31) / 32, (64 + 31) / 32, B_), tb>>>(f0, 0);
    transpose_kernel<<<dim3((784 + 31) / 32, (128 + 31) / 32, B_), tb>>>(f1, 1);
    transpose_kernel<<<dim3((196 + 31) / 32, (256 + 31) / 32, B_), tb>>>(f2, 2);
    transpose_kernel<<<dim3((49 + 31) / 32, (512 + 31) / 32, B_), tb>>>(f3, 3);

    int total = B_ * N_ * 240;   // float4 elements = 15,728,640
    int blocks = (total + 255) / 256;
    proj_kernel<<<blocks, 256>>>(pc, (float4*)d_out, total);
}

// round 5
// speedup vs baseline: 1.0125x; 1.0125x over previous
#include <cuda_runtime.h>
#include <cstdint>

// ---------------------------------------------------------------------------
// FeatureProjection: 4-level bilinear gather + concat
//   feat0 [16, 64,56,56], feat1 [16,128,28,28], feat2 [16,256,14,14],
//   feat3 [16,512, 7, 7], pc [16,4096,3]  ->  out [16,4096,960] fp32
//
//   1) single fused transpose kernel: all levels NCHW -> NHWC scratch.
//   2) proj kernel over B*N*240 float4 outputs with ZERO-WEIGHT EARLY-OUT:
//      ~83% of coords saturate the clip; integer coords give all-zero
//      bilinear weights -> skip the 4 corner gathers entirely.
//   NUMERICS: XLA folds /(223/(W-1)) into * f32(1/f32(223/(W-1))).
// ---------------------------------------------------------------------------

#define B_    16
#define N_    4096

__device__ __align__(16) float g_t0[16 * 56 * 56 * 64];
__device__ __align__(16) float g_t1[16 * 28 * 28 * 128];
__device__ __align__(16) float g_t2[16 * 14 * 14 * 256];
__device__ __align__(16) float g_t3[16 * 7 * 7 * 512];

__host__ __device__ constexpr float kC0 = (float)(223.0 / 55.0);
__host__ __device__ constexpr float kC1 = (float)(223.0 / 27.0);
__host__ __device__ constexpr float kC2 = (float)(223.0 / 13.0);
__host__ __device__ constexpr float kC3 = (float)(223.0 / 6.0);

// ------------- fused transpose: [C, HW] -> [HW, C], all 4 levels ------------
// tile-pair counts per level (32x32 tiles, 32x8 threads):
//   L0: ceil(3136/32)=98 x ceil(64/32)=2  = 196
//   L1: ceil(784/32) =25 x ceil(128/32)=4 = 100
//   L2: ceil(196/32) = 7 x ceil(256/32)=8 =  56
//   L3: ceil(49/32)  = 2 x ceil(512/32)=16=  32
// cumulative: 196, 296, 352, 384  (grid.x = 384, grid.z = B)
__global__ void transpose_all_kernel(const float* __restrict__ f0,
                                     const float* __restrict__ f1,
                                     const float* __restrict__ f2,
                                     const float* __restrict__ f3)
{
    __shared__ float tile[32][33];

    int t = blockIdx.x;
    const float* in; float* out;
    int C, HW, stiles, local;
    if (t < 196)      { in = f0; out = g_t0; C = 64;  HW = 3136; stiles = 98; local = t; }
    else if (t < 296) { in = f1; out = g_t1; C = 128; HW = 784;  stiles = 25; local = t - 196; }
    else if (t < 352) { in = f2; out = g_t2; C = 256; HW = 196;  stiles = 7;  local = t - 296; }
    else              { in = f3; out = g_t3; C = 512; HW = 49;   stiles = 2;  local = t - 352; }

    int ctile = local / stiles;
    int stile = local - ctile * stiles;

    const int b = blockIdx.z;
    const float* bin  = in  + (size_t)b * C * HW;
    float*       bout = out + (size_t)b * C * HW;

    int s0 = stile * 32;
    int c0 = ctile * 32;

    int s = s0 + threadIdx.x;
    #pragma unroll
    for (int j = 0; j < 32; j += 8) {
        int c = c0 + threadIdx.y + j;
        if (s < HW && c < C)
            tile[threadIdx.y + j][threadIdx.x] = bin[(size_t)c * HW + s];
    }
    __syncthreads();

    int c = c0 + threadIdx.x;
    #pragma unroll
    for (int j = 0; j < 32; j += 8) {
        int ss = s0 + threadIdx.y + j;
        if (c < C && ss < HW)
            bout[(size_t)ss * C + c] = tile[threadIdx.x][threadIdx.y + j];
    }
}

// ---------------- main projection kernel -----------------------------------
// float4 outputs per point: 16 + 32 + 64 + 128 = 240
// level boundaries (float4 units): [0,16) [16,48) [48,112) [112,240)
__global__ void __launch_bounds__(256) proj_kernel(const float* __restrict__ pc,
                                                   float4* __restrict__ out,
                                                   int total)
{
    int idx = blockIdx.x * blockDim.x + threadIdx.x;
    if (idx >= total) return;

    int point = idx / 240;
    int i     = idx - point * 240;
    int b     = point >> 12;          // N = 4096

    const float* pp = pc + (size_t)point * 3;
    float X = __ldg(pp + 0);
    float Y = __ldg(pp + 1);
    float Z = __ldg(pp + 2);

    const float4* base;
    int c4, H, C4;
    float rscale;   // f32 reciprocal of the f32 constant, XLA's folded form
    if (i < 16)       { base = (const float4*)g_t0; c4 = i;       H = 56; C4 = 16;  rscale = 1.0f / kC0; }
    else if (i < 48)  { base = (const float4*)g_t1; c4 = i - 16;  H = 28; C4 = 32;  rscale = 1.0f / kC1; }
    else if (i < 112) { base = (const float4*)g_t2; c4 = i - 48;  H = 14; C4 = 64;  rscale = 1.0f / kC2; }
    else              { base = (const float4*)g_t3; c4 = i - 112; H = 7;  C4 = 128; rscale = 1.0f / kC3; }
    const int W = H;

    float az = fabsf(Z);
    float w = fminf(fmaxf(__fdiv_rn(420.0f * X, az) + 111.5f, 0.0f), 223.0f);
    float h = fminf(fmaxf(__fdiv_rn(420.0f * Y, az) + 111.5f, 0.0f), 223.0f);
    float x = __fmul_rn(w, rscale);
    float y = __fmul_rn(h, rscale);

    float x1f = floorf(x), x2f = ceilf(x);
    float y1f = floorf(y), y2f = ceilf(y);

    // EARLY OUT: integer coordinate on either axis -> all 4 bilinear weights
    // are exactly zero -> output 0, skip all gathers. Warp-coherent branch.
    if (x1f == x2f || y1f == y2f) {
        out[idx] = make_float4(0.0f, 0.0f, 0.0f, 0.0f);
        return;
    }

    float w11 = (x2f - x) * (y2f - y);
    float w21 = (x - x1f) * (y2f - y);
    float w12 = (x2f - x) * (y - y1f);
    float w22 = (x - x1f) * (y - y1f);

    // gather indices clamped (XLA gather clamps OOB; ceil can hit W here)
    int x1 = min(max((int)x1f, 0), W - 1);
    int x2 = min(max((int)x2f, 0), W - 1);
    int y1 = min(max((int)y1f, 0), W - 1);
    int y2 = min(max((int)y2f, 0), W - 1);

    const float4* pb = base + (size_t)b * H * W * C4;
    int r1 = x1 * W * C4;
    int r2 = x2 * W * C4;
    float4 v11 = __ldg(pb + r1 + y1 * C4 + c4);
    float4 v21 = __ldg(pb + r2 + y1 * C4 + c4);
    float4 v12 = __ldg(pb + r1 + y2 * C4 + c4);
    float4 v22 = __ldg(pb + r2 + y2 * C4 + c4);

    float4 r;
    r.x = v11.x * w11 + v21.x * w21 + v12.x * w12 + v22.x * w22;
    r.y = v11.y * w11 + v21.y * w21 + v12.y * w12 + v22.y * w22;
    r.z = v11.z * w11 + v21.z * w21 + v12.z * w12 + v22.z * w22;
    r.w = v11.w * w11 + v21.w * w21 + v12.w * w12 + v22.w * w22;

    out[idx] = r;
}

// ---------------------------------------------------------------------------
extern "C" void kernel_launch(void* const* d_in, const int* in_sizes, int n_in,
                              void* d_out, int out_size)
{
    const float* f0 = (const float*)d_in[0];
    const float* f1 = (const float*)d_in[1];
    const float* f2 = (const float*)d_in[2];
    const float* f3 = (const float*)d_in[3];
    const float* pc = (const float*)d_in[4];

    dim3 tb(32, 8, 1);
    transpose_all_kernel<<<dim3(384, 1, B_), tb>>>(f0, f1, f2, f3);

    int total = B_ * N_ * 240;   // float4 elements = 15,728,640
    int blocks = (total + 255) / 256;
    proj_kernel<<<blocks, 256>>>(pc, (float4*)d_out, total);
}

// round 6
// speedup vs baseline: 1.1300x; 1.1161x over previous
#include <cuda_runtime.h>
#include <cstdint>

// ---------------------------------------------------------------------------
// FeatureProjection: 4-level bilinear gather + concat
//   feat0 [16, 64,56,56], feat1 [16,128,28,28], feat2 [16,256,14,14],
//   feat3 [16,512, 7, 7], pc [16,4096,3]  ->  out [16,4096,960] fp32
//
//   1) fused transpose kernel: all levels NCHW -> NHWC scratch (L2-resident).
//   2) proj kernel: ONE BLOCK PER POINT. Threads 0-3 compute the projection
//      params (bilinear weights + gather offsets) for the 4 levels once into
//      smem; the 240 worker threads only do 4 gathers + 16 FMA + 1 store.
//      Zero-weight (integer-coordinate) cells are branch-free: weights=0,
//      offsets=0 -> broadcast L1 hit, exact-zero result.
//   NUMERICS: XLA folds /(223/(W-1)) into * f32(1/f32(223/(W-1))).
// ---------------------------------------------------------------------------

#define B_    16
#define N_    4096

__device__ __align__(16) float g_t0[16 * 56 * 56 * 64];
__device__ __align__(16) float g_t1[16 * 28 * 28 * 128];
__device__ __align__(16) float g_t2[16 * 14 * 14 * 256];
__device__ __align__(16) float g_t3[16 * 7 * 7 * 512];

__host__ __device__ constexpr float kC0 = (float)(223.0 / 55.0);
__host__ __device__ constexpr float kC1 = (float)(223.0 / 27.0);
__host__ __device__ constexpr float kC2 = (float)(223.0 / 13.0);
__host__ __device__ constexpr float kC3 = (float)(223.0 / 6.0);

// ------------- fused transpose: [C, HW] -> [HW, C], all 4 levels ------------
__global__ void transpose_all_kernel(const float* __restrict__ f0,
                                     const float* __restrict__ f1,
                                     const float* __restrict__ f2,
                                     const float* __restrict__ f3)
{
    __shared__ float tile[32][33];

    int t = blockIdx.x;
    const float* in; float* out;
    int C, HW, stiles, local;
    if (t < 196)      { in = f0; out = g_t0; C = 64;  HW = 3136; stiles = 98; local = t; }
    else if (t < 296) { in = f1; out = g_t1; C = 128; HW = 784;  stiles = 25; local = t - 196; }
    else if (t < 352) { in = f2; out = g_t2; C = 256; HW = 196;  stiles = 7;  local = t - 296; }
    else              { in = f3; out = g_t3; C = 512; HW = 49;   stiles = 2;  local = t - 352; }

    int ctile = local / stiles;
    int stile = local - ctile * stiles;

    const int b = blockIdx.z;
    const float* bin  = in  + (size_t)b * C * HW;
    float*       bout = out + (size_t)b * C * HW;

    int s0 = stile * 32;
    int c0 = ctile * 32;

    int s = s0 + threadIdx.x;
    #pragma unroll
    for (int j = 0; j < 32; j += 8) {
        int c = c0 + threadIdx.y + j;
        if (s < HW && c < C)
            tile[threadIdx.y + j][threadIdx.x] = bin[(size_t)c * HW + s];
    }
    __syncthreads();

    int c = c0 + threadIdx.x;
    #pragma unroll
    for (int j = 0; j < 32; j += 8) {
        int ss = s0 + threadIdx.y + j;
        if (c < C && ss < HW)
            bout[(size_t)ss * C + c] = tile[threadIdx.x][threadIdx.y + j];
    }
}

// ---------------- main projection kernel: one block per point ---------------
// float4 outputs per point: 16 + 32 + 64 + 128 = 240
// level boundaries (float4 units): [0,16) [16,48) [48,112) [112,240)
__global__ void __launch_bounds__(256) proj_kernel(const float* __restrict__ pc,
                                                   float4* __restrict__ out)
{
    __shared__ float4 s_w[4];   // w11,w21,w12,w22 per level
    __shared__ int4   s_o[4];   // gather offsets (float4 units) per level

    const int point = blockIdx.x;
    const int b     = point >> 12;      // N = 4096

    if (threadIdx.x < 4) {
        const int lvl = threadIdx.x;
        // per-level constants
        const int   Htab[4]   = {56, 28, 14, 7};
        const int   C4tab[4]  = {16, 32, 64, 128};
        const float rtab[4]   = {1.0f / kC0, 1.0f / kC1, 1.0f / kC2, 1.0f / kC3};
        const int H = Htab[lvl], W = H, C4 = C4tab[lvl];
        const float rscale = rtab[lvl];

        const float* pp = pc + (size_t)point * 3;
        float X = __ldg(pp + 0);
        float Y = __ldg(pp + 1);
        float Z = __ldg(pp + 2);

        float az = fabsf(Z);
        float w = fminf(fmaxf(__fdiv_rn(420.0f * X, az) + 111.5f, 0.0f), 223.0f);
        float h = fminf(fmaxf(__fdiv_rn(420.0f * Y, az) + 111.5f, 0.0f), 223.0f);
        float x = __fmul_rn(w, rscale);
        float y = __fmul_rn(h, rscale);

        float x1f = floorf(x), x2f = ceilf(x);
        float y1f = floorf(y), y2f = ceilf(y);

        bool zero = (x1f == x2f) || (y1f == y2f);

        float w11 = (x2f - x) * (y2f - y);
        float w21 = (x - x1f) * (y2f - y);
        float w12 = (x2f - x) * (y - y1f);
        float w22 = (x - x1f) * (y - y1f);

        int x1 = min(max((int)x1f, 0), W - 1);
        int x2 = min(max((int)x2f, 0), W - 1);
        int y1 = min(max((int)y1f, 0), W - 1);
        int y2 = min(max((int)y2f, 0), W - 1);

        int bb = b * H * W * C4;        // batch base, float4 units
        int r1 = bb + x1 * W * C4;
        int r2 = bb + x2 * W * C4;
        int o11 = r1 + y1 * C4;
        int o21 = r2 + y1 * C4;
        int o12 = r1 + y2 * C4;
        int o22 = r2 + y2 * C4;

        if (zero) {                     // branch-free downstream: 0-weights,
            w11 = w21 = w12 = w22 = 0.0f;   // offset 0 -> broadcast L1 hit
            o11 = o21 = o12 = o22 = 0;
        }
        s_w[lvl] = make_float4(w11, w21, w12, w22);
        s_o[lvl] = make_int4(o11, o21, o12, o22);
    }
    __syncthreads();

    const int i = threadIdx.x;
    if (i >= 240) return;

    const float4* base;
    int lvl, c4;
    if (i < 16)       { lvl = 0; c4 = i;       base = (const float4*)g_t0; }
    else if (i < 48)  { lvl = 1; c4 = i - 16;  base = (const float4*)g_t1; }
    else if (i < 112) { lvl = 2; c4 = i - 48;  base = (const float4*)g_t2; }
    else              { lvl = 3; c4 = i - 112; base = (const float4*)g_t3; }

    float4 wv = s_w[lvl];
    int4   ov = s_o[lvl];

    float4 v11 = __ldg(base + ov.x + c4);
    float4 v21 = __ldg(base + ov.y + c4);
    float4 v12 = __ldg(base + ov.z + c4);
    float4 v22 = __ldg(base + ov.w + c4);

    float4 r;
    r.x = v11.x * wv.x + v21.x * wv.y + v12.x * wv.z + v22.x * wv.w;
    r.y = v11.y * wv.x + v21.y * wv.y + v12.y * wv.z + v22.y * wv.w;
    r.z = v11.z * wv.x + v21.z * wv.y + v12.z * wv.z + v22.z * wv.w;
    r.w = v11.w * wv.x + v21.w * wv.y + v12.w * wv.z + v22.w * wv.w;

    out[(size_t)point * 240 + i] = r;
}

// ---------------------------------------------------------------------------
extern "C" void kernel_launch(void* const* d_in, const int* in_sizes, int n_in,
                              void* d_out, int out_size)
{
    const float* f0 = (const float*)d_in[0];
    const float* f1 = (const float*)d_in[1];
    const float* f2 = (const float*)d_in[2];
    const float* f3 = (const float*)d_in[3];
    const float* pc = (const float*)d_in[4];

    dim3 tb(32, 8, 1);
    transpose_all_kernel<<<dim3(384, 1, B_), tb>>>(f0, f1, f2, f3);

    proj_kernel<<<B_ * N_, 256>>>(pc, (float4*)d_out);
}